// round 9
// baseline (speedup 1.0000x reference)
#include <cuda_runtime.h>
#include <math.h>

#define BATCH 4096
#define FEAT  4096
#define THREADS 512
#define GRID BATCH   // one row per block

__global__ __launch_bounds__(THREADS)
void fused_loss_kernel(const float* __restrict__ o1,
                       const float* __restrict__ o2,
                       const float* __restrict__ o3,
                       float* __restrict__ out) {
    const int row = blockIdx.x;
    const size_t base = (size_t)row * FEAT;
    const float4* __restrict__ a = reinterpret_cast<const float4*>(o1 + base);
    const float4* __restrict__ b = reinterpret_cast<const float4*>(o2 + base);
    const float4* __restrict__ c = reinterpret_cast<const float4*>(o3 + base);

    const int tid  = threadIdx.x;
    const int lane = tid & 31;
    const int wid  = tid >> 5;

    float s13 = 0.0f;
    float s12 = 0.0f;

    // 1024 float4 per row / 512 threads = 2 iterations. unroll 1 keeps only
    // 3 LDG.128 front-batched per body (oe*MLP_p1 = 9 < 16 threshold) ->
    // avoids cross-CTA L1tex-queue spread; 48 warps/SM cover latency.
#pragma unroll 1
    for (int it = 0; it < (FEAT / 4) / THREADS; ++it) {
        int i = tid + it * THREADS;
        float4 x = a[i];
        float4 y = b[i];
        float4 z = c[i];

        float d;
        d = x.x - z.x; s13 = fmaf(d, d, s13);
        d = x.y - z.y; s13 = fmaf(d, d, s13);
        d = x.z - z.z; s13 = fmaf(d, d, s13);
        d = x.w - z.w; s13 = fmaf(d, d, s13);

        d = x.x - y.x; s12 = fmaf(d, d, s12);
        d = x.y - y.y; s12 = fmaf(d, d, s12);
        d = x.z - y.z; s12 = fmaf(d, d, s12);
        d = x.w - y.w; s12 = fmaf(d, d, s12);
    }

#pragma unroll
    for (int off = 16; off > 0; off >>= 1) {
        s13 += __shfl_down_sync(0xFFFFFFFFu, s13, off);
        s12 += __shfl_down_sync(0xFFFFFFFFu, s12, off);
    }

    __shared__ float sm13[THREADS / 32];
    __shared__ float sm12[THREADS / 32];
    if (lane == 0) { sm13[wid] = s13; sm12[wid] = s12; }
    __syncthreads();

    if (tid == 0) {
        float t13 = 0.0f, t12 = 0.0f;
#pragma unroll
        for (int w = 0; w < THREADS / 32; ++w) { t13 += sm13[w]; t12 += sm12[w]; }
        float compare = 2.0f - sqrtf(t13) + sqrtf(t12);
        float hinged = fmaxf(0.0f, compare);
        // Broadcast-sum over [B,B] == B * sum_b(hinged). One overlapped ATOMG
        // per block; out[] zeroed by cudaMemsetAsync in kernel_launch.
        atomicAdd(out, hinged * (float)BATCH);
    }
}

extern "C" void kernel_launch(void* const* d_in, const int* in_sizes, int n_in,
                              void* d_out, int out_size) {
    const float* o1 = (const float*)d_in[0];
    const float* o2 = (const float*)d_in[1];
    const float* o3 = (const float*)d_in[2];
    float* out = (float*)d_out;

    cudaMemsetAsync(out, 0, sizeof(float));
    fused_loss_kernel<<<GRID, THREADS>>>(o1, o2, o3, out);
}

// round 10
// speedup vs baseline: 1.0254x; 1.0254x over previous
#include <cuda_runtime.h>
#include <math.h>

#define BATCH 4096
#define FEAT  4096
#define THREADS 512
#define GRID   444   // 148 SMs x 3 resident CTAs: persistent, work-stealing

// Scratch (device globals; no allocation allowed).
__device__ unsigned int g_ctr    = 0u;   // row work queue
__device__ float        g_acc    = 0.0f; // loss accumulator
__device__ unsigned int g_ticket = 0u;   // completion ticket

__global__ __launch_bounds__(THREADS, 3)
void fused_loss_kernel(const float* __restrict__ o1,
                       const float* __restrict__ o2,
                       const float* __restrict__ o3,
                       float* __restrict__ out) {
    const int tid  = threadIdx.x;
    const int lane = tid & 31;
    const int wid  = tid >> 5;

    __shared__ float        sm13[2][THREADS / 32];
    __shared__ float        sm12[2][THREADS / 32];
    __shared__ unsigned int s_row;

    float block_sum = 0.0f;   // only meaningful in thread 0
    int   p = 0;

    if (tid == 0) s_row = atomicAdd(&g_ctr, 1u);
    __syncthreads();
    unsigned int row = s_row;

    while (row < BATCH) {
        const size_t base = (size_t)row * FEAT;
        const float4* __restrict__ a = reinterpret_cast<const float4*>(o1 + base);
        const float4* __restrict__ b = reinterpret_cast<const float4*>(o2 + base);
        const float4* __restrict__ c = reinterpret_cast<const float4*>(o3 + base);

        float s13 = 0.0f;
        float s12 = 0.0f;

#pragma unroll
        for (int it = 0; it < (FEAT / 4) / THREADS; ++it) {
            int i = tid + it * THREADS;
            float4 x = a[i];
            float4 y = b[i];
            float4 z = c[i];

            float d;
            d = x.x - z.x; s13 = fmaf(d, d, s13);
            d = x.y - z.y; s13 = fmaf(d, d, s13);
            d = x.z - z.z; s13 = fmaf(d, d, s13);
            d = x.w - z.w; s13 = fmaf(d, d, s13);

            d = x.x - y.x; s12 = fmaf(d, d, s12);
            d = x.y - y.y; s12 = fmaf(d, d, s12);
            d = x.z - y.z; s12 = fmaf(d, d, s12);
            d = x.w - y.w; s12 = fmaf(d, d, s12);
        }

#pragma unroll
        for (int off = 16; off > 0; off >>= 1) {
            s13 += __shfl_down_sync(0xFFFFFFFFu, s13, off);
            s12 += __shfl_down_sync(0xFFFFFFFFu, s12, off);
        }

        if (lane == 0) { sm13[p][wid] = s13; sm12[p][wid] = s12; }
        if (tid == 0)  s_row = atomicAdd(&g_ctr, 1u);   // steal next row
        __syncthreads();   // single barrier per row (double-buffered smem)

        if (tid == 0) {
            float t13 = 0.0f, t12 = 0.0f;
#pragma unroll
            for (int w = 0; w < THREADS / 32; ++w) {
                t13 += sm13[p][w]; t12 += sm12[p][w];
            }
            float compare = 2.0f - sqrtf(t13) + sqrtf(t12);
            block_sum += fmaxf(0.0f, compare);
        }
        row = s_row;   // written before the barrier, safe to read
        p ^= 1;
    }

    // One relaxed ATOMG per block, then fence-free release ticket publish.
    if (tid == 0) {
        atomicAdd(&g_acc, block_sum);

        unsigned int old;
        asm volatile("atom.release.gpu.global.add.u32 %0, [%1], %2;"
                     : "=r"(old) : "l"(&g_ticket), "r"(1u) : "memory");

        if (old == GRID - 1) {
            float total;
            asm volatile("ld.acquire.gpu.global.f32 %0, [%1];"
                         : "=f"(total) : "l"(&g_acc) : "memory");
            out[0] = total * (float)BATCH;   // broadcast-sum over [B,B]
            // Reset scratch for the next graph replay.
            g_acc = 0.0f;
            g_ctr = 0u;
            asm volatile("st.release.gpu.global.u32 [%0], %1;"
                         :: "l"(&g_ticket), "r"(0u) : "memory");
        }
    }
}

extern "C" void kernel_launch(void* const* d_in, const int* in_sizes, int n_in,
                              void* d_out, int out_size) {
    const float* o1 = (const float*)d_in[0];
    const float* o2 = (const float*)d_in[1];
    const float* o3 = (const float*)d_in[2];
    float* out = (float*)d_out;

    fused_loss_kernel<<<GRID, THREADS>>>(o1, o2, o3, out);
}

// round 11
// speedup vs baseline: 1.0357x; 1.0101x over previous
#include <cuda_runtime.h>
#include <math.h>

#define BATCH 4096
#define FEAT  4096
#define THREADS 1024
#define GRID BATCH   // one row per block, one float4-triple per thread

__global__ __launch_bounds__(THREADS, 2)   // force <=32 regs -> 64 warps/SM (100% occ)
void fused_loss_kernel(const float* __restrict__ o1,
                       const float* __restrict__ o2,
                       const float* __restrict__ o3,
                       float* __restrict__ out) {
    const int row = blockIdx.x;
    const size_t base = (size_t)row * FEAT;
    const float4* __restrict__ a = reinterpret_cast<const float4*>(o1 + base);
    const float4* __restrict__ b = reinterpret_cast<const float4*>(o2 + base);
    const float4* __restrict__ c = reinterpret_cast<const float4*>(o3 + base);

    const int tid  = threadIdx.x;
    const int lane = tid & 31;
    const int wid  = tid >> 5;

    // Exactly one float4 per tensor per thread: 3 LDG.128, minimal registers.
    float4 x = a[tid];
    float4 y = b[tid];
    float4 z = c[tid];

    float s13 = 0.0f;
    float s12 = 0.0f;
    float d;
    d = x.x - z.x; s13 = fmaf(d, d, s13);
    d = x.y - z.y; s13 = fmaf(d, d, s13);
    d = x.z - z.z; s13 = fmaf(d, d, s13);
    d = x.w - z.w; s13 = fmaf(d, d, s13);

    d = x.x - y.x; s12 = fmaf(d, d, s12);
    d = x.y - y.y; s12 = fmaf(d, d, s12);
    d = x.z - y.z; s12 = fmaf(d, d, s12);
    d = x.w - y.w; s12 = fmaf(d, d, s12);

#pragma unroll
    for (int off = 16; off > 0; off >>= 1) {
        s13 += __shfl_down_sync(0xFFFFFFFFu, s13, off);
        s12 += __shfl_down_sync(0xFFFFFFFFu, s12, off);
    }

    __shared__ float sm13[THREADS / 32];
    __shared__ float sm12[THREADS / 32];
    if (lane == 0) { sm13[wid] = s13; sm12[wid] = s12; }
    __syncthreads();

    // Final 32-wide reduction in warp 0 via shuffles (32 warps per block).
    if (wid == 0) {
        float t13 = sm13[lane];
        float t12 = sm12[lane];
#pragma unroll
        for (int off = 16; off > 0; off >>= 1) {
            t13 += __shfl_down_sync(0xFFFFFFFFu, t13, off);
            t12 += __shfl_down_sync(0xFFFFFFFFu, t12, off);
        }
        if (lane == 0) {
            float compare = 2.0f - sqrtf(t13) + sqrtf(t12);
            float hinged = fmaxf(0.0f, compare);
            // Broadcast-sum over [B,B] == B * sum_b(hinged). One overlapped
            // ATOMG per block; out[] zeroed by cudaMemsetAsync below.
            atomicAdd(out, hinged * (float)BATCH);
        }
    }
}

extern "C" void kernel_launch(void* const* d_in, const int* in_sizes, int n_in,
                              void* d_out, int out_size) {
    const float* o1 = (const float*)d_in[0];
    const float* o2 = (const float*)d_in[1];
    const float* o3 = (const float*)d_in[2];
    float* out = (float*)d_out;

    cudaMemsetAsync(out, 0, sizeof(float));
    fused_loss_kernel<<<GRID, THREADS>>>(o1, o2, o3, out);
}